// round 17
// baseline (speedup 1.0000x reference)
#include <cuda_runtime.h>
#include <cuda_fp16.h>
#include <cstdint>

#define BN 8192
#define TN 223
#define DN 7
#define HN 128
#define EN 50
#define ON 29
#define AN 9
#define NTHR 256
#define NTHRM 512
#define NBLK 128
#define NE 64

#define YH_OFF 3
#define IMP_OFF (3 + BN*ON)
#define LBL_OFF (IMP_OFF + BN*TN*DN)

#define STW 136
#define STE 24
#define STV 152
#define OFF_WH 0
#define OFF_WE 139264
#define OFF_VH 163840
#define OFF_VL 183296
#define OFF_F  202752
#define FXD 0
#define FMD 896
#define FDD 1792
#define FXH 2688
#define FXC 3136
#define FGX 3584
#define FWF 4032
#define FWCB 4081
#define FBH 4179
#define FBF 4186
#define FBC 4193
#define FTDX 4200
#define FBTDX 4207
#define FWHT 4216
#define FRED 5240
#define NFLT 5248
#define SMEM_TOTAL (OFF_F + NFLT*4)

#define HBAR() asm volatile("bar.sync %0, %1;" :: "r"(1 + hb), "r"(256) : "memory")

__device__ __align__(16) unsigned char g_wimg[163840];
__device__ float4 g_b4[HN];
__device__ float  g_part[4][TN];
__device__ float  g_yloss;

__device__ __forceinline__ uint32_t smem_u32(const void* p) {
    uint32_t a;
    asm("{ .reg .u64 t; cvta.to.shared.u64 t, %1; cvt.u32.u64 %0, t; }" : "=r"(a) : "l"(p));
    return a;
}
__device__ __forceinline__ void ldsm4(uint32_t& a0, uint32_t& a1, uint32_t& a2, uint32_t& a3, uint32_t ad) {
    asm volatile("ldmatrix.sync.aligned.m8n8.x4.shared.b16 {%0,%1,%2,%3}, [%4];"
                 : "=r"(a0), "=r"(a1), "=r"(a2), "=r"(a3) : "r"(ad));
}
__device__ __forceinline__ void ldsm2(uint32_t& b0, uint32_t& b1, uint32_t ad) {
    asm volatile("ldmatrix.sync.aligned.m8n8.x2.shared.b16 {%0,%1}, [%2];"
                 : "=r"(b0), "=r"(b1) : "r"(ad));
}
__device__ __forceinline__ void mmaop(float* d, uint32_t a0, uint32_t a1, uint32_t a2, uint32_t a3,
                                      uint32_t b0, uint32_t b1) {
    asm volatile("mma.sync.aligned.m16n8k16.row.col.f32.f16.f16.f32 "
                 "{%0,%1,%2,%3}, {%4,%5,%6,%7}, {%8,%9}, {%0,%1,%2,%3};"
                 : "+f"(d[0]), "+f"(d[1]), "+f"(d[2]), "+f"(d[3])
                 : "r"(a0), "r"(a1), "r"(a2), "r"(a3), "r"(b0), "r"(b1));
}
__device__ __forceinline__ float tanhfast(float x) {
    float r; asm("tanh.approx.f32 %0, %1;" : "=f"(r) : "f"(x)); return r;
}
__device__ __forceinline__ float sigf(float x) { return fmaf(tanhfast(0.5f * x), 0.5f, 0.5f); }

__global__ void rits_prep(const float* __restrict__ Wih, const float* __restrict__ Whh,
                          const float* __restrict__ bih, const float* __restrict__ bhh) {
    int i = blockIdx.x * blockDim.x + threadIdx.x;
    if (i < 512 * STW) {
        int r = i / STW, k = i - r * STW;
        ((__half*)g_wimg)[i] = __float2half((k < HN) ? Whh[r * HN + k] : 0.f);
    }
    if (i < 512 * STE) {
        int r = i / STE, c = i - r * STE;
        ((__half*)(g_wimg + OFF_WE))[i] = __float2half((c < 2 * DN) ? Wih[r * 2 * DN + c] : 0.f);
    }
    if (i < HN)
        g_b4[i] = make_float4(bih[i] + bhh[i], bih[HN + i] + bhh[HN + i],
                              bih[2*HN + i] + bhh[2*HN + i], bih[3*HN + i] + bhh[3*HN + i]);
    if (i < 4 * TN) ((float*)g_part)[i] = 0.f;
    if (i == 0) g_yloss = 0.f;
}

__global__ void __launch_bounds__(NTHRM) rits_main(
    const float* __restrict__ values,  const float* __restrict__ masks,
    const float* __restrict__ deltas,  const float* __restrict__ probs,
    const float* __restrict__ ancillary, const int* __restrict__ labels,
    const float* __restrict__ W_td_h,  const float* __restrict__ b_td_h,
    const float* __restrict__ W_td_x,  const float* __restrict__ b_td_x,
    const float* __restrict__ W_hist,  const float* __restrict__ b_hist,
    const float* __restrict__ W_feat,  const float* __restrict__ b_feat,
    const float* __restrict__ W_comb,  const float* __restrict__ b_comb,
    const float* __restrict__ W_anc,   const float* __restrict__ b_anc,
    const float* __restrict__ W_cat,   const float* __restrict__ b_cat,
    const float* __restrict__ W_out,   const float* __restrict__ b_out,
    float* __restrict__ out)
{
    extern __shared__ __align__(16) unsigned char sm[];
    float* F = (float*)(sm + OFF_F);
    const uint32_t sb = smem_u32(sm);
    const int tid = threadIdx.x, lane = tid & 31, w = tid >> 5;
    const int gid = lane >> 2, tig = lane & 3;
    const int jb = 16 * (w & 7);
    const int hb = w >> 3;                  // half id (0/1)
    const int ntb = hb * 4;
    const int ltid = tid & 255;             // half-local tid
    const int eb = blockIdx.x * NE;

    for (int i = tid; i < 163840/16; i += NTHRM) ((uint4*)sm)[i] = ((const uint4*)g_wimg)[i];
    for (int i = tid; i < 38912/16; i += NTHRM) ((uint4*)(sm + OFF_VH))[i] = make_uint4(0,0,0,0);
    if (tid < 49) { int a = tid/7, b = tid%7; F[FWF+tid] = (a==b) ? 0.f : W_feat[tid]; }
    if (tid >= 64 && tid < 162) F[FWCB + tid - 64] = W_comb[tid - 64];
    if (tid >= 192 && tid < 199) {
        int k = tid - 192;
        F[FBH+k] = b_hist[k]; F[FBF+k] = b_feat[k]; F[FBC+k] = b_comb[k];
        F[FTDX+k] = W_td_x[k*DN+k]; F[FBTDX+k] = b_td_x[k];
    }
    if (tid >= 224 && tid < 232) F[FRED + tid - 224] = 0.f;
    for (int i = tid; i < 1024; i += NTHRM) {
        int j = i >> 3, k = i & 7;
        F[FWHT + i] = (k < DN) ? W_hist[k * HN + j] : 0.f;
    }
    if (tid < 448) {
        int k = tid >> 6, e = tid & 63;
        size_t o = (size_t)(eb + e) * TN * DN + k;
        F[FXD+tid] = values[o]; F[FMD+tid] = masks[o]; F[FDD+tid] = deltas[o];
    }

    const int j1 = jb + gid, j2 = j1 + 8;
    float wtdA[DN], wtdB[DN];
#pragma unroll
    for (int k = 0; k < DN; k++) { wtdA[k] = W_td_h[j1*DN+k]; wtdB[k] = W_td_h[j2*DN+k]; }
    const float btdA = b_td_h[j1], btdB = b_td_h[j2];
    const float4 b4a = g_b4[j1], b4b = g_b4[j2];

    uint32_t aW[4], aEx[4];
#pragma unroll
    for (int g = 0; g < 4; g++) {
        aW[g]  = sb + OFF_WH + (uint32_t)((g*128 + jb) + (lane & 15)) * (2*STW) + (lane >> 4) * 16;
        aEx[g] = sb + OFF_WE + (uint32_t)((g*128 + jb) + (lane & 15)) * (2*STE) + (lane >> 4) * 16;
    }
    const uint32_t aVh = sb + OFF_VH + (uint32_t)(lane & 7) * (2*STV) + ((lane >> 3) & 1) * 16;
    const uint32_t aVl = sb + OFF_VL + (uint32_t)(lane & 7) * (2*STV) + ((lane >> 3) & 1) * 16;

    float cst[16];
#pragma unroll
    for (int i = 0; i < 16; i++) cst[i] = 0.f;
    __syncthreads();

    for (int t = 0; t < TN; ++t) {
        const int cur = t & 1, alt = cur ^ 1;

        // ---- Phase A (fused x_h + D1 + gamma_x + prefetch), half-local ----
        {
            const int e = hb*32 + (ltid >> 3);
            const int q = tid & 7;
            const int j0 = q * 16;
            const __half* vh = (const __half*)(sm + OFF_VH) + e * STV + j0;
            const __half* vl = (const __half*)(sm + OFF_VL) + e * STV + j0;
            float a[DN] = {0.f, 0.f, 0.f, 0.f, 0.f, 0.f, 0.f};
#pragma unroll
            for (int bq = 0; bq < 2; bq++) {
                uint4 uh = *(const uint4*)(vh + bq * 8);
                uint4 ul = *(const uint4*)(vl + bq * 8);
                const uint32_t* ph = (const uint32_t*)&uh;
                const uint32_t* pl = (const uint32_t*)&ul;
#pragma unroll
                for (int p2 = 0; p2 < 4; p2++) {
                    float2 fh = __half22float2(*(const __half2*)&ph[p2]);
                    float2 fl = __half22float2(*(const __half2*)&pl[p2]);
                    float h0 = fh.x + fl.x, h1 = fh.y + fl.y;
                    const float* w0 = F + FWHT + (j0 + bq*8 + p2*2) * 8;
#pragma unroll
                    for (int k = 0; k < DN; k++)
                        a[k] = fmaf(w0[k], h0, fmaf(w0[8 + k], h1, a[k]));
                }
            }
#pragma unroll
            for (int k = 0; k < DN; k++) {
                a[k] += __shfl_xor_sync(0xffffffffu, a[k], 1);
                a[k] += __shfl_xor_sync(0xffffffffu, a[k], 2);
                a[k] += __shfl_xor_sync(0xffffffffu, a[k], 4);
            }
            if (q == 0) {                   // D1 for this e
                float l0 = 0.f, l1 = 0.f;
#pragma unroll
                for (int k = 0; k < DN; k++) {
                    float xh = a[k] + F[FBH + k];
                    float x = F[FXD + cur*448 + k*64 + e], m = F[FMD + cur*448 + k*64 + e];
                    F[FXC + k*64 + e] = m * x + (1.f - m) * xh;
                    l0 += m; l1 += m * fabsf(x - xh);
                }
                atomicAdd(&F[FRED + hb*4], l0);
                atomicAdd(&F[FRED + hb*4 + 1], l1);
            } else if (q == 1) {
#pragma unroll
                for (int k = 0; k < DN; k++) F[FXH + k*64 + e] = a[k] + F[FBH + k];
            } else if (q == 2) {
#pragma unroll
                for (int k = 0; k < DN; k++) {
                    float d = F[FDD + cur*448 + k*64 + e];
                    F[FGX + k*64 + e] = __expf(-fmaxf(d * F[FTDX + k] + F[FBTDX + k], 0.f));
                }
            } else if (q == 3 && t + 1 < TN) {
#pragma unroll
                for (int k = 0; k < DN; k++)
                    F[FXD + alt*448 + k*64 + e] = values[((size_t)(eb + e) * TN + (t + 1)) * DN + k];
            } else if (q == 4 && t + 1 < TN) {
#pragma unroll
                for (int k = 0; k < DN; k++)
                    F[FMD + alt*448 + k*64 + e] = masks[((size_t)(eb + e) * TN + (t + 1)) * DN + k];
            } else if (q == 5 && t + 1 < TN) {
#pragma unroll
                for (int k = 0; k < DN; k++)
                    F[FDD + alt*448 + k*64 + e] = deltas[((size_t)(eb + e) * TN + (t + 1)) * DN + k];
            }
        }
        HBAR();

        // ---- Phase B (D2), half-local: 224 items ----
        {
            float l2 = 0.f, l3 = 0.f;
            if (ltid < 224) {
                int k = ltid >> 5, e = hb*32 + (ltid & 31);
                float x = F[FXD + cur*448 + k*64 + e], m = F[FMD + cur*448 + k*64 + e];
                float xh = F[FXH + k*64 + e];
                float z = F[FBF + k];
#pragma unroll
                for (int k2 = 0; k2 < DN; k2++) z = fmaf(F[FWF + k*7 + k2], F[FXC + k2*64 + e], z);
                l2 = m * fabsf(x - z);
                float al = F[FBC + k];
#pragma unroll
                for (int k2 = 0; k2 < DN; k2++) {
                    al = fmaf(F[FWCB + k*14 + k2], F[FGX + k2*64 + e], al);
                    al = fmaf(F[FWCB + k*14 + 7 + k2], F[FMD + cur*448 + k2*64 + e], al);
                }
                float ch = al * z + (1.f - al) * xh;
                l3 = m * fabsf(x - ch);
                float cc = m * x + (1.f - m) * ch;
                out[IMP_OFF + ((size_t)(eb + e) * TN + t) * DN + k] = cc;
                *((__half*)(sm + OFF_VH) + e * STV + 128 + k) = __float2half(cc);
                *((__half*)(sm + OFF_VH) + e * STV + 135 + k) = __float2half(m);
            }
#pragma unroll
            for (int o = 16; o > 0; o >>= 1) {
                l2 += __shfl_down_sync(0xffffffffu, l2, o);
                l3 += __shfl_down_sync(0xffffffffu, l3, o);
            }
            if (lane == 0) { atomicAdd(&F[FRED + hb*4 + 2], l2); atomicAdd(&F[FRED + hb*4 + 3], l3); }
        }
        HBAR();

        if (ltid == 0) {
#pragma unroll
            for (int r = 0; r < 4; r++) {
                atomicAdd(&g_part[r][t], F[FRED + hb*4 + r]);
                F[FRED + hb*4 + r] = 0.f;
            }
        }

        // ---- MMA + epilogue: 2 n-quarters of this half ----
#pragma unroll 1
        for (int nh = 0; nh < 2; nh++) {
            float acc[4][2][4];
#pragma unroll
            for (int g = 0; g < 4; g++)
#pragma unroll
                for (int n2 = 0; n2 < 2; n2++)
#pragma unroll
                    for (int i = 0; i < 4; i++) acc[g][n2][i] = 0.f;
#pragma unroll 1
            for (int kc = 0; kc < 8; kc++) {
                uint32_t A0[4], A1[4], A2[4], A3[4];
#pragma unroll
                for (int g = 0; g < 4; g++) ldsm4(A0[g], A1[g], A2[g], A3[g], aW[g] + kc * 32);
#pragma unroll
                for (int n2 = 0; n2 < 2; n2++) {
                    int nt = ntb + nh*2 + n2;
                    uint32_t boff = (uint32_t)nt * (16*STV) + kc * 32;
                    uint32_t b0, b1;
                    ldsm2(b0, b1, aVh + boff);
#pragma unroll
                    for (int g = 0; g < 4; g++) mmaop(acc[g][n2], A0[g], A1[g], A2[g], A3[g], b0, b1);
                    ldsm2(b0, b1, aVl + boff);
#pragma unroll
                    for (int g = 0; g < 4; g++) mmaop(acc[g][n2], A0[g], A1[g], A2[g], A3[g], b0, b1);
                }
            }
            {
                uint32_t A0[4], A1[4], A2[4], A3[4];
#pragma unroll
                for (int g = 0; g < 4; g++) ldsm4(A0[g], A1[g], A2[g], A3[g], aEx[g]);
#pragma unroll
                for (int n2 = 0; n2 < 2; n2++) {
                    int nt = ntb + nh*2 + n2;
                    uint32_t b0, b1;
                    ldsm2(b0, b1, aVh + (uint32_t)nt * (16*STV) + 256);
#pragma unroll
                    for (int g = 0; g < 4; g++) mmaop(acc[g][n2], A0[g], A1[g], A2[g], A3[g], b0, b1);
                }
            }
            HBAR();
#pragma unroll
            for (int n2 = 0; n2 < 2; n2++) {
#pragma unroll
                for (int ee = 0; ee < 2; ee++) {
                    int e = (ntb + nh*2 + n2) * 8 + 2*tig + ee;
                    float gaA = 1.f, gaB = 1.f;
                    if (t + 1 < TN) {
                        float sA = btdA, sB = btdB;
#pragma unroll
                        for (int k = 0; k < DN; k++) {
                            float dv = F[FDD + alt*448 + k*64 + e];
                            sA = fmaf(wtdA[k], dv, sA);
                            sB = fmaf(wtdB[k], dv, sB);
                        }
                        gaA = __expf(-fmaxf(sA, 0.f));
                        gaB = __expf(-fmaxf(sB, 0.f));
                    }
#pragma unroll
                    for (int jj = 0; jj < 2; jj++) {
                        const float4 bv = jj ? b4b : b4a;
                        int di = jj*2 + ee;
                        float gi = sigf(acc[0][n2][di] + bv.x);
                        float gf = sigf(acc[1][n2][di] + bv.y);
                        float gg = tanhfast(acc[2][n2][di] + bv.z);
                        float go = sigf(acc[3][n2][di] + bv.w);
                        int ci = (nh*2 + n2)*4 + jj*2 + ee;
                        float cn = gf * cst[ci] + gi * gg;
                        cst[ci] = cn;
                        float hd = go * tanhfast(cn) * (jj ? gaB : gaA);
                        __half hi = __float2half(hd);
                        int jv = jj ? j2 : j1;
                        *((__half*)(sm + OFF_VH) + e * STV + jv) = hi;
                        *((__half*)(sm + OFF_VL) + e * STV + jv) = __float2half(hd - __half2float(hi));
                    }
                }
            }
        }
        HBAR();
    }

    // ================= head =================
    __syncthreads();                      // re-join halves before overwriting weight smem
    float* ht  = (float*)sm;
    float* hc  = (float*)(sm + 32768);
    float* anc = (float*)(sm + 65536);
    float* lg  = (float*)(sm + 78336);
    for (int it = tid; it < HN * 64; it += NTHRM) {
        int jj = it >> 6, e = it & 63;
        ht[it] = __half2float(*((const __half*)(sm + OFF_VH) + e * STV + jj))
               + __half2float(*((const __half*)(sm + OFF_VL) + e * STV + jj));
    }
    for (int it = tid; it < EN * 64; it += NTHRM) {
        int q = it >> 6, e = it & 63;
        const float* ar = ancillary + (size_t)(eb + e) * AN;
        float a = b_anc[q];
#pragma unroll
        for (int k = 0; k < AN; k++) a = fmaf(ar[k], W_anc[q * AN + k], a);
        anc[it] = fmaxf(a, 0.f);
    }
    __syncthreads();
    {
        int jh = tid >> 2, qt = tid & 3;
        const float* wc = W_cat + (size_t)jh * (HN + EN);
        float a2[16];
        float bc = b_cat[jh];
#pragma unroll
        for (int c = 0; c < 16; c++) a2[c] = bc;
        for (int jj = 0; jj < HN; jj++) {
            float wv = wc[jj];
            const float* hr = ht + jj * 64 + qt * 16;
#pragma unroll
            for (int c = 0; c < 16; c++) a2[c] = fmaf(wv, hr[c], a2[c]);
        }
        for (int q = 0; q < EN; q++) {
            float wv = wc[HN + q];
            const float* arow = anc + q * 64 + qt * 16;
#pragma unroll
            for (int c = 0; c < 16; c++) a2[c] = fmaf(wv, arow[c], a2[c]);
        }
#pragma unroll
        for (int c = 0; c < 16; c++) hc[jh * 64 + qt * 16 + c] = fmaxf(a2[c], 0.f);
    }
    __syncthreads();
    for (int it = tid; it < ON * 64; it += NTHRM) {
        int o = it >> 6, e = it & 63;
        const float* wo = W_out + (size_t)o * HN;
        float a = b_out[o];
#pragma unroll 8
        for (int jj = 0; jj < HN; jj++) a = fmaf(hc[jj * 64 + e], wo[jj], a);
        lg[it] = a;
    }
    __syncthreads();
    if (tid < 64) {
        int e = tid;
        float mx = -1e30f;
        for (int o = 0; o < ON; o++) mx = fmaxf(mx, lg[o * 64 + e]);
        float s = 0.f;
        for (int o = 0; o < ON; o++) s += __expf(lg[o * 64 + e] - mx);
        float inv = __fdividef(1.f, s);
        const float* pr = probs + (size_t)(eb + e) * ON;
        float* yo = out + YH_OFF + (size_t)(eb + e) * ON;
        float yl = 0.f;
        for (int o = 0; o < ON; o++) {
            float y = __expf(lg[o * 64 + e] - mx) * inv;
            yo[o] = y;
            float dd = y - pr[o];
            yl += dd * dd;
        }
        atomicAdd(&g_yloss, yl);
        out[LBL_OFF + eb + e] = (float)labels[eb + e];
    }
}

__global__ void rits_finalize(float* __restrict__ out) {
    __shared__ float s[NTHR];
    int t = threadIdx.x;
    float v = 0.f;
    if (t < TN)
        v = (g_part[1][t] + g_part[2][t] + g_part[3][t]) / (g_part[0][t] + 1e-5f);
    s[t] = v;
    __syncthreads();
    for (int st = NTHR / 2; st > 0; st >>= 1) {
        if (t < st) s[t] += s[t + st];
        __syncthreads();
    }
    if (t == 0) {
        float xl = 0.3f * s[0];
        float yl = g_yloss / (8192.0f + 1e-5f);
        out[0] = xl; out[1] = yl; out[2] = xl + yl;
    }
}

extern "C" void kernel_launch(void* const* d_in, const int* in_sizes, int n_in,
                              void* d_out, int out_size) {
    (void)in_sizes; (void)n_in; (void)out_size;
    const float* values    = (const float*)d_in[0];
    const float* masks     = (const float*)d_in[1];
    const float* deltas    = (const float*)d_in[2];
    const float* probs     = (const float*)d_in[3];
    const float* ancillary = (const float*)d_in[4];
    const int*   labels    = (const int*)  d_in[5];
    const float* W_td_h = (const float*)d_in[6];
    const float* b_td_h = (const float*)d_in[7];
    const float* W_td_x = (const float*)d_in[8];
    const float* b_td_x = (const float*)d_in[9];
    const float* W_hist = (const float*)d_in[10];
    const float* b_hist = (const float*)d_in[11];
    const float* W_feat = (const float*)d_in[12];
    const float* b_feat = (const float*)d_in[13];
    const float* W_comb = (const float*)d_in[14];
    const float* b_comb = (const float*)d_in[15];
    const float* W_ih   = (const float*)d_in[16];
    const float* W_hh   = (const float*)d_in[17];
    const float* b_ih   = (const float*)d_in[18];
    const float* b_hh   = (const float*)d_in[19];
    const float* W_anc  = (const float*)d_in[20];
    const float* b_anc  = (const float*)d_in[21];
    const float* W_cat  = (const float*)d_in[22];
    const float* b_cat  = (const float*)d_in[23];
    const float* W_out  = (const float*)d_in[24];
    const float* b_out  = (const float*)d_in[25];
    float* out = (float*)d_out;

    cudaFuncSetAttribute(rits_main, cudaFuncAttributeMaxDynamicSharedMemorySize, SMEM_TOTAL);
    rits_prep<<<272, NTHR>>>(W_ih, W_hh, b_ih, b_hh);
    rits_main<<<NBLK, NTHRM, SMEM_TOTAL>>>(values, masks, deltas, probs, ancillary, labels,
                                           W_td_h, b_td_h, W_td_x, b_td_x, W_hist, b_hist,
                                           W_feat, b_feat, W_comb, b_comb,
                                           W_anc, b_anc, W_cat, b_cat, W_out, b_out, out);
    rits_finalize<<<1, NTHR>>>(out);
}